// round 2
// baseline (speedup 1.0000x reference)
#include <cuda_runtime.h>
#include <math.h>

// Problem constants
#define NN 100000
#define EE 1600000
#define ET (EE + NN)      // edges + self loops
#define FF 128            // feature dim everywhere (IN = H*C = 128)
#define HH 4
#define CC 32
#define NEG_SLOPE 0.2f

// ----------------------------------------------------------------------------
// Scratch (device globals; no allocations allowed)
// ----------------------------------------------------------------------------
__device__ float g_h[(size_t)NN * FF];     // transformed features of current layer
__device__ float g_feat[(size_t)NN * FF];  // input features for layers 1,2
__device__ float g_es[NN * HH];
__device__ float g_ed[NN * HH];
__device__ int   g_off[NN + 1];
__device__ int   g_cur[NN];                // counts, then write cursors
__device__ int   g_csr[ET];                // src node per CSR slot (grouped by dst)
__device__ int   g_is64;                   // 1 if edge_index is int64, 0 if int32

// ----------------------------------------------------------------------------
// Edge index dtype probe: int64 values < 2^31 have zero high 32-bit words at
// odd word positions. Random int32 node ids (in [0,100000)) can't be all zero
// across 128 samples.
// ----------------------------------------------------------------------------
__global__ void k_detect(const int* __restrict__ ei32) {
    if (threadIdx.x == 0) {
        int all0 = 1;
        for (int j = 1; j < 256; j += 2)
            if (ei32[j] != 0) { all0 = 0; break; }
        g_is64 = all0;
    }
}

__device__ __forceinline__ int load_edge(const void* ei, size_t idx) {
    if (g_is64) return (int)((const long long*)ei)[idx];
    return ((const int*)ei)[idx];
}

// ----------------------------------------------------------------------------
// CSR build (counting sort by dst). Runs every launch (graph replay).
// ----------------------------------------------------------------------------
__global__ void k_init_counts() {
    int n = blockIdx.x * blockDim.x + threadIdx.x;
    if (n < NN) g_cur[n] = 1;  // self loop
}

__global__ void k_count(const void* __restrict__ ei) {
    int i = blockIdx.x * blockDim.x + threadIdx.x;
    if (i < EE) {
        int d = load_edge(ei, (size_t)EE + i);
        atomicAdd(&g_cur[d], 1);
    }
}

// Exclusive scan of g_cur[0..NN) into g_off, reset g_cur to offsets.
__global__ void k_scan() {
    __shared__ int ps[1024];
    const int CH = 98;  // 1024*98 = 100352 >= NN
    int t = threadIdx.x;
    int base = t * CH;
    int s = 0;
    for (int i = 0; i < CH; i++) {
        int idx = base + i;
        if (idx < NN) s += g_cur[idx];
    }
    ps[t] = s;
    __syncthreads();
    for (int off = 1; off < 1024; off <<= 1) {
        int v = (t >= off) ? ps[t - off] : 0;
        __syncthreads();
        ps[t] += v;
        __syncthreads();
    }
    int run = ps[t] - s;  // exclusive prefix
    for (int i = 0; i < CH; i++) {
        int idx = base + i;
        if (idx < NN) {
            int c = g_cur[idx];
            g_off[idx] = run;
            g_cur[idx] = run;
            run += c;
        }
    }
    if (t == 1023) g_off[NN] = ps[1023];
}

__global__ void k_scatter(const void* __restrict__ ei) {
    int i = blockIdx.x * blockDim.x + threadIdx.x;
    if (i >= ET) return;
    int s, d;
    if (i < EE) {
        s = load_edge(ei, i);
        d = load_edge(ei, (size_t)EE + i);
    } else {
        s = d = i - EE;  // self loop
    }
    int p = atomicAdd(&g_cur[d], 1);
    g_csr[p] = s;
}

// ----------------------------------------------------------------------------
// GEMM: Y[g_h] = X[N,128] @ W[128,128]. 64-row tile, k-tiled by 32.
// 256 threads; thread owns 8 rows x 4 cols.
// ----------------------------------------------------------------------------
__global__ void __launch_bounds__(256) k_gemm(const float* __restrict__ Xext,
                                              const float* __restrict__ W,
                                              int use_gfeat) {
    const float* X = use_gfeat ? g_feat : Xext;
    __shared__ float sX[64 * 32];
    __shared__ float sW[32 * 128];
    float4* sX4 = (float4*)sX;
    float4* sW4 = (float4*)sW;

    int tid = threadIdx.x;
    int row0 = blockIdx.x * 64;
    int cg = tid & 31;   // col group: cols 4*cg..4*cg+3
    int rg = tid >> 5;   // row group: rows rg*8..rg*8+7

    float acc[8][4] = {};

    for (int kt = 0; kt < 4; kt++) {
        int k0 = kt * 32;
        // load X tile: 64 x 32 = 512 float4
#pragma unroll
        for (int j = 0; j < 2; j++) {
            int idx = tid + 256 * j;
            int r = idx >> 3, c4 = idx & 7;
            float4 v = make_float4(0.f, 0.f, 0.f, 0.f);
            int gr = row0 + r;
            if (gr < NN) v = *(const float4*)(X + (size_t)gr * FF + k0 + 4 * c4);
            sX4[idx] = v;
        }
        // load W tile: 32 x 128 = 1024 float4
#pragma unroll
        for (int j = 0; j < 4; j++) {
            int idx = tid + 256 * j;
            int r = idx >> 5, c4 = idx & 31;
            sW4[idx] = *(const float4*)(W + (size_t)(k0 + r) * FF + 4 * c4);
        }
        __syncthreads();
#pragma unroll
        for (int kk = 0; kk < 32; kk++) {
            float4 w = sW4[kk * 32 + cg];
#pragma unroll
            for (int i = 0; i < 8; i++) {
                float xv = sX[(rg * 8 + i) * 32 + kk];
                acc[i][0] += xv * w.x;
                acc[i][1] += xv * w.y;
                acc[i][2] += xv * w.z;
                acc[i][3] += xv * w.w;
            }
        }
        __syncthreads();
    }
#pragma unroll
    for (int i = 0; i < 8; i++) {
        int gr = row0 + rg * 8 + i;
        if (gr < NN) {
            float4 v = make_float4(acc[i][0], acc[i][1], acc[i][2], acc[i][3]);
            *(float4*)(g_h + (size_t)gr * FF + 4 * cg) = v;
        }
    }
}

// ----------------------------------------------------------------------------
// Attention coefficients: es[n][h] = sum_c h[n,h,c]*as[h,c]; ed likewise.
// 128 threads = 4 warps = 4 heads; warp reduce.
// ----------------------------------------------------------------------------
__global__ void __launch_bounds__(128) k_attn(const float* __restrict__ a_src,
                                              const float* __restrict__ a_dst) {
    int t = threadIdx.x;
    float asv = a_src[t];
    float adv = a_dst[t];
    int hd = t >> 5;
    for (int n = blockIdx.x; n < NN; n += gridDim.x) {
        float v = g_h[(size_t)n * FF + t];
        float vs = v * asv;
        float vd = v * adv;
#pragma unroll
        for (int o = 16; o; o >>= 1) {
            vs += __shfl_xor_sync(0xffffffffu, vs, o);
            vd += __shfl_xor_sync(0xffffffffu, vd, o);
        }
        if ((t & 31) == 0) {
            g_es[n * HH + hd] = vs;
            g_ed[n * HH + hd] = vd;
        }
    }
}

// ----------------------------------------------------------------------------
// Edge phase: per dst node, softmax over incoming edges (no max needed:
// softmax is shift-invariant and |e| is small) + weighted aggregation.
// One 128-thread block per node; thread t owns channel t (head t>>5).
// ----------------------------------------------------------------------------
__global__ void __launch_bounds__(128) k_edge(const float* __restrict__ bias,
                                              float* __restrict__ out_ext,
                                              int last) {
    __shared__ int   s_src[32];
    __shared__ float s_w[32][4];
    __shared__ float s_ed[4];

    int node = blockIdx.x;
    int t = threadIdx.x;
    int hd = t >> 5;
    int beg = g_off[node];
    int end = g_off[node + 1];

    if (t < 4) s_ed[t] = g_ed[node * HH + t];
    __syncthreads();

    float acc = 0.f;
    float wsum = 0.f;

    for (int base = beg; base < end; base += 32) {
        int m = min(32, end - base);
        if (t < m) {
            int s = g_csr[base + t];
            s_src[t] = s;
#pragma unroll
            for (int k = 0; k < 4; k++) {
                float z = g_es[s * HH + k] + s_ed[k];
                z = (z > 0.f) ? z : NEG_SLOPE * z;
                s_w[t][k] = __expf(z);
            }
        }
        __syncthreads();
#pragma unroll 4
        for (int j = 0; j < m; j++) {
            float w = s_w[j][hd];
            int s = s_src[j];
            acc += w * __ldg(&g_h[(size_t)s * FF + t]);
            wsum += w;
        }
        __syncthreads();
    }

    float o = acc / wsum + bias[t];
    if (!last) o = (o > 0.f) ? o : (__expf(o) - 1.f);
    float* out = last ? out_ext : g_feat;
    out[(size_t)node * FF + t] = o;
}

// ----------------------------------------------------------------------------
// Launch
// ----------------------------------------------------------------------------
extern "C" void kernel_launch(void* const* d_in, const int* in_sizes, int n_in,
                              void* d_out, int out_size) {
    const float* x  = (const float*)d_in[0];
    const void*  ei = d_in[1];
    const float* W[3]  = {(const float*)d_in[2], (const float*)d_in[6],  (const float*)d_in[10]};
    const float* AS[3] = {(const float*)d_in[3], (const float*)d_in[7],  (const float*)d_in[11]};
    const float* AD[3] = {(const float*)d_in[4], (const float*)d_in[8],  (const float*)d_in[12]};
    const float* B[3]  = {(const float*)d_in[5], (const float*)d_in[9],  (const float*)d_in[13]};
    float* out = (float*)d_out;

    // CSR build
    k_detect<<<1, 32>>>((const int*)ei);
    k_init_counts<<<(NN + 255) / 256, 256>>>();
    k_count<<<(EE + 255) / 256, 256>>>(ei);
    k_scan<<<1, 1024>>>();
    k_scatter<<<(ET + 255) / 256, 256>>>(ei);

    const int gemm_blocks = (NN + 63) / 64;

    for (int L = 0; L < 3; L++) {
        k_gemm<<<gemm_blocks, 256>>>(x, W[L], L > 0 ? 1 : 0);
        k_attn<<<4096, 128>>>(AS[L], AD[L]);
        k_edge<<<NN, 128>>>(B[L], out, L == 2 ? 1 : 0);
    }
}

// round 4
// speedup vs baseline: 1.3038x; 1.3038x over previous
#include <cuda_runtime.h>
#include <math.h>

// Problem constants
#define NN 100000
#define EE 1600000
#define ET (EE + NN)      // edges + self loops
#define FF 128            // feature dim everywhere (IN = H*C = 128)
#define HH 4
#define CC 32
#define NEG_SLOPE 0.2f
#define SCAN_B 98         // 98 * 1024 >= NN

// ----------------------------------------------------------------------------
// Scratch (device globals; no allocations allowed)
// ----------------------------------------------------------------------------
__device__ float g_h[(size_t)NN * FF];     // transformed features of current layer
__device__ float g_feat[(size_t)NN * FF];  // input features for layers 1,2
__device__ __align__(16) float g_es[NN * HH];
__device__ __align__(16) float g_ed[NN * HH];
__device__ int   g_off[NN + 1];
__device__ int   g_cur[NN];                // counts, then cursors
__device__ int   g_csr[ET];                // src node per CSR slot (grouped by dst)
__device__ int   g_bsum[SCAN_B];
__device__ int   g_is64;                   // 1 if edge_index is int64, 0 if int32

// ----------------------------------------------------------------------------
// Edge index dtype probe (JAX may give int32 or int64)
// ----------------------------------------------------------------------------
__global__ void k_detect(const int* __restrict__ ei32) {
    if (threadIdx.x == 0) {
        int all0 = 1;
        for (int j = 1; j < 256; j += 2)
            if (ei32[j] != 0) { all0 = 0; break; }
        g_is64 = all0;
    }
}

__device__ __forceinline__ int load_edge(const void* ei, size_t idx) {
    if (g_is64) return (int)((const long long*)ei)[idx];
    return ((const int*)ei)[idx];
}

// ----------------------------------------------------------------------------
// CSR build: counting sort by dst
// ----------------------------------------------------------------------------
__global__ void k_init_counts() {
    int n = blockIdx.x * blockDim.x + threadIdx.x;
    if (n < NN) g_cur[n] = 1;  // self loop
}

__global__ void k_count(const void* __restrict__ ei) {
    int i = blockIdx.x * blockDim.x + threadIdx.x;
    if (i < EE) {
        int d = load_edge(ei, (size_t)EE + i);
        atomicAdd(&g_cur[d], 1);
    }
}

// Per-block sums of counts (coalesced)
__global__ void __launch_bounds__(1024) k_blocksum() {
    __shared__ int sh[32];
    int t = threadIdx.x;
    int g = blockIdx.x * 1024 + t;
    int c = (g < NN) ? g_cur[g] : 0;
#pragma unroll
    for (int o = 16; o; o >>= 1) c += __shfl_xor_sync(0xffffffffu, c, o);
    if ((t & 31) == 0) sh[t >> 5] = c;
    __syncthreads();
    if (t < 32) {
        int v = sh[t];
#pragma unroll
        for (int o = 16; o; o >>= 1) v += __shfl_xor_sync(0xffffffffu, v, o);
        if (t == 0) g_bsum[blockIdx.x] = v;
    }
}

// Exclusive scan of the 98 block sums (tiny)
__global__ void k_scan_top() {
    __shared__ int sh[SCAN_B];
    int t = threadIdx.x;
    if (t < SCAN_B) sh[t] = g_bsum[t];
    __syncthreads();
    if (t == 0) {
        int run = 0;
        for (int i = 0; i < SCAN_B; i++) { int c = sh[i]; sh[i] = run; run += c; }
    }
    __syncthreads();
    if (t < SCAN_B) g_bsum[t] = sh[t];
}

// Per-block exclusive scan + base offset
__global__ void __launch_bounds__(1024) k_scan_final() {
    __shared__ int sh[1024];
    int t = threadIdx.x;
    int g = blockIdx.x * 1024 + t;
    int c = (g < NN) ? g_cur[g] : 0;
    sh[t] = c;
    __syncthreads();
#pragma unroll
    for (int off = 1; off < 1024; off <<= 1) {
        int v = (t >= off) ? sh[t - off] : 0;
        __syncthreads();
        sh[t] += v;
        __syncthreads();
    }
    int excl = sh[t] - c + g_bsum[blockIdx.x];
    if (g < NN) {
        g_off[g] = excl;
        g_cur[g] = excl;
    }
    if (g == 0) g_off[NN] = ET;  // total is a compile-time constant
}

__global__ void k_scatter(const void* __restrict__ ei) {
    int i = blockIdx.x * blockDim.x + threadIdx.x;
    if (i >= ET) return;
    int s, d;
    if (i < EE) {
        s = load_edge(ei, i);
        d = load_edge(ei, (size_t)EE + i);
    } else {
        s = d = i - EE;  // self loop
    }
    int p = atomicAdd(&g_cur[d], 1);
    g_csr[p] = s;
}

// ----------------------------------------------------------------------------
// GEMM: g_h = X[N,128] @ W[128,128], with fused attention-coefficient epilogue.
// 64-row tile, k-tiled by 32; 256 threads; thread owns 8 rows x 4 cols.
// A thread's 4 columns (4*cg..4*cg+3) all lie in head cg>>3, so es/ed reduce
// over 8-lane groups of the warp (warp == row group).
// ----------------------------------------------------------------------------
__global__ void __launch_bounds__(256) k_gemm(const float* __restrict__ Xext,
                                              const float* __restrict__ W,
                                              const float* __restrict__ a_src,
                                              const float* __restrict__ a_dst,
                                              int use_gfeat) {
    const float* X = use_gfeat ? g_feat : Xext;
    __shared__ float sX[64 * 32];
    __shared__ float sW[32 * 128];
    float4* sX4 = (float4*)sX;
    float4* sW4 = (float4*)sW;

    int tid = threadIdx.x;
    int row0 = blockIdx.x * 64;
    int cg = tid & 31;   // col group: cols 4*cg..4*cg+3 (also lane id)
    int rg = tid >> 5;   // row group (warp id): rows rg*8..rg*8+7

    float acc[8][4] = {};

    for (int kt = 0; kt < 4; kt++) {
        int k0 = kt * 32;
#pragma unroll
        for (int j = 0; j < 2; j++) {
            int idx = tid + 256 * j;
            int r = idx >> 3, c4 = idx & 7;
            float4 v = make_float4(0.f, 0.f, 0.f, 0.f);
            int gr = row0 + r;
            if (gr < NN) v = *(const float4*)(X + (size_t)gr * FF + k0 + 4 * c4);
            sX4[idx] = v;
        }
#pragma unroll
        for (int j = 0; j < 4; j++) {
            int idx = tid + 256 * j;
            int r = idx >> 5, c4 = idx & 31;
            sW4[idx] = *(const float4*)(W + (size_t)(k0 + r) * FF + 4 * c4);
        }
        __syncthreads();
#pragma unroll
        for (int kk = 0; kk < 32; kk++) {
            float4 w = sW4[kk * 32 + cg];
#pragma unroll
            for (int i = 0; i < 8; i++) {
                float xv = sX[(rg * 8 + i) * 32 + kk];
                acc[i][0] += xv * w.x;
                acc[i][1] += xv * w.y;
                acc[i][2] += xv * w.z;
                acc[i][3] += xv * w.w;
            }
        }
        __syncthreads();
    }

    float4 asv = *(const float4*)(a_src + 4 * cg);
    float4 adv = *(const float4*)(a_dst + 4 * cg);
    int head = cg >> 3;

#pragma unroll
    for (int i = 0; i < 8; i++) {
        int gr = row0 + rg * 8 + i;
        float vs = acc[i][0] * asv.x + acc[i][1] * asv.y + acc[i][2] * asv.z + acc[i][3] * asv.w;
        float vd = acc[i][0] * adv.x + acc[i][1] * adv.y + acc[i][2] * adv.z + acc[i][3] * adv.w;
#pragma unroll
        for (int o = 4; o; o >>= 1) {
            vs += __shfl_xor_sync(0xffffffffu, vs, o);
            vd += __shfl_xor_sync(0xffffffffu, vd, o);
        }
        if (gr < NN) {
            *(float4*)(g_h + (size_t)gr * FF + 4 * cg) =
                make_float4(acc[i][0], acc[i][1], acc[i][2], acc[i][3]);
            if ((cg & 7) == 0) {
                g_es[gr * HH + head] = vs;
                g_ed[gr * HH + head] = vd;
            }
        }
    }
}

// ----------------------------------------------------------------------------
// Edge phase: per dst node, max-free softmax over incoming edges + aggregation.
// One 128-thread block per node; thread t owns channel t (head t>>5).
// ----------------------------------------------------------------------------
__global__ void __launch_bounds__(128) k_edge(const float* __restrict__ bias,
                                              float* __restrict__ out_ext,
                                              int last) {
    __shared__ int   s_src[32];
    __shared__ float s_w[32][4];
    __shared__ float s_ed[4];

    int node = blockIdx.x;
    int t = threadIdx.x;
    int hd = t >> 5;
    int beg = g_off[node];
    int end = g_off[node + 1];

    if (t < 4) s_ed[t] = g_ed[node * HH + t];
    __syncthreads();

    float acc = 0.f;
    float wsum = 0.f;

    for (int base = beg; base < end; base += 32) {
        int m = min(32, end - base);
        if (t < m) {
            int s = g_csr[base + t];
            s_src[t] = s;
            float4 e = *(const float4*)(g_es + s * HH);
            float z0 = e.x + s_ed[0]; z0 = (z0 > 0.f) ? z0 : NEG_SLOPE * z0;
            float z1 = e.y + s_ed[1]; z1 = (z1 > 0.f) ? z1 : NEG_SLOPE * z1;
            float z2 = e.z + s_ed[2]; z2 = (z2 > 0.f) ? z2 : NEG_SLOPE * z2;
            float z3 = e.w + s_ed[3]; z3 = (z3 > 0.f) ? z3 : NEG_SLOPE * z3;
            s_w[t][0] = __expf(z0);
            s_w[t][1] = __expf(z1);
            s_w[t][2] = __expf(z2);
            s_w[t][3] = __expf(z3);
        }
        __syncthreads();
#pragma unroll 4
        for (int j = 0; j < m; j++) {
            float w = s_w[j][hd];
            int s = s_src[j];
            acc += w * __ldg(&g_h[(size_t)s * FF + t]);
            wsum += w;
        }
        __syncthreads();
    }

    float o = acc / wsum + bias[t];
    if (!last) o = (o > 0.f) ? o : (__expf(o) - 1.f);
    float* out = last ? out_ext : g_feat;
    out[(size_t)node * FF + t] = o;
}

// ----------------------------------------------------------------------------
// Launch
// ----------------------------------------------------------------------------
extern "C" void kernel_launch(void* const* d_in, const int* in_sizes, int n_in,
                              void* d_out, int out_size) {
    const float* x  = (const float*)d_in[0];
    const void*  ei = d_in[1];
    const float* W[3]  = {(const float*)d_in[2], (const float*)d_in[6],  (const float*)d_in[10]};
    const float* AS[3] = {(const float*)d_in[3], (const float*)d_in[7],  (const float*)d_in[11]};
    const float* AD[3] = {(const float*)d_in[4], (const float*)d_in[8],  (const float*)d_in[12]};
    const float* B[3]  = {(const float*)d_in[5], (const float*)d_in[9],  (const float*)d_in[13]};
    float* out = (float*)d_out;

    // CSR build
    k_detect<<<1, 32>>>((const int*)ei);
    k_init_counts<<<(NN + 255) / 256, 256>>>();
    k_count<<<(EE + 255) / 256, 256>>>(ei);
    k_blocksum<<<SCAN_B, 1024>>>();
    k_scan_top<<<1, 128>>>();
    k_scan_final<<<SCAN_B, 1024>>>();
    k_scatter<<<(ET + 255) / 256, 256>>>(ei);

    const int gemm_blocks = (NN + 63) / 64;

    for (int L = 0; L < 3; L++) {
        k_gemm<<<gemm_blocks, 256>>>(x, W[L], AS[L], AD[L], L > 0 ? 1 : 0);
        k_edge<<<NN, 128>>>(B[L], out, L == 2 ? 1 : 0);
    }
}